// round 9
// baseline (speedup 1.0000x reference)
#include <cuda_runtime.h>
#include <math.h>

#define BB 64
#define DD 256
#define LL 2048
#define HH 512
#define KC 128

// ---------------- scratch (device globals: allocation-free) ----------------
__device__ float g_v [BB * DD * LL];   // current v (B, D, L)
__device__ float g_h [BB * DD * LL];   // LN output (tf32-rounded) (B, D, L)
__device__ float g_stat[BB * 2 * DD];  // [mu over L | sd over L]
__device__ float g_qk  [BB * DD];      // scale * wk^T @ q  (per-batch D-vector)
__device__ float g_wsm [BB * LL];      // softmax weights
__device__ float g_am  [BB * DD];      // att_mean
__device__ float g_as  [BB * DD];      // att_std
__device__ float g_qadd[BB * DD];      // fcq_w @ att_mean
__device__ float g_skip[BB * DD];      // skip_sum accumulator
// tf32-rounded weight copies
__device__ float g_w1[2 * HH * DD];
__device__ float g_w2[2 * DD * HH];

__device__ __forceinline__ float tf32r(float x) {
    float y;
    asm("cvt.rna.tf32.f32 %0, %1;" : "=f"(y) : "f"(x));
    return y;
}

// ---------------- one-time weight rounding ----------------
__global__ void prep_kernel(const float* __restrict__ w1,
                            const float* __restrict__ w2) {
    const int NW1 = 2 * HH * DD, NW2 = 2 * DD * HH;
    int i = blockIdx.x * 256 + threadIdx.x;
    int stride = gridDim.x * 256;
    for (int p = i; p < NW1; p += stride) g_w1[p] = tf32r(w1[p]);
    for (int p = i; p < NW2; p += stride) g_w2[p] = tf32r(w2[p]);
}

// ---------------- LayerNorm over channel dim (att path): src -> g_h --------
__global__ void att_ln_kernel(const float* __restrict__ src,
                              const float* __restrict__ gam,
                              const float* __restrict__ bet) {
    __shared__ float sg[DD], sb[DD];
    int t = threadIdx.x;
    sg[t] = gam[t]; sb[t] = bet[t];
    __syncthreads();
    int p = blockIdx.x * 256 + t;
    int b = p / LL, l = p % LL;
    const float* base = src + (size_t)b * DD * LL + l;
    float s = 0.f, s2 = 0.f;
    #pragma unroll 8
    for (int d = 0; d < DD; d++) {
        float x = base[(size_t)d * LL];
        s += x; s2 += x * x;
    }
    float mu = s * (1.f / DD);
    float var = s2 * (1.f / DD) - mu * mu;
    float rs = rsqrtf(var + 1e-6f);
    float* out = g_h + (size_t)b * DD * LL + l;
    #pragma unroll 8
    for (int d = 0; d < DD; d++) {
        float x = base[(size_t)d * LL];
        out[(size_t)d * LL] = tf32r((x - mu) * rs * sg[d] + sb[d]);
    }
}

// ---- FFN LN: reads src+qadd, writes LN(f_in) into g_h (f_in NOT stored;
//      the fused FFN epilogue recomputes f_in = v_old + qadd inline) -------
__global__ void ffn_ln_kernel(const float* __restrict__ src,
                              const float* __restrict__ gam,
                              const float* __restrict__ bet) {
    __shared__ float sg[DD], sb[DD], sq[DD];
    int t = threadIdx.x;
    int b = (blockIdx.x * 256) / LL;
    sg[t] = gam[t]; sb[t] = bet[t]; sq[t] = g_qadd[b * DD + t];
    __syncthreads();
    int p = blockIdx.x * 256 + t;
    int l = p % LL;
    const float* base = src + (size_t)b * DD * LL + l;
    float s = 0.f, s2 = 0.f;
    #pragma unroll 8
    for (int d = 0; d < DD; d++) {
        float x = base[(size_t)d * LL] + sq[d];
        s += x; s2 += x * x;
    }
    float mu = s * (1.f / DD);
    float var = s2 * (1.f / DD) - mu * mu;
    float rs = rsqrtf(var + 1e-6f);
    float* out = g_h + (size_t)b * DD * LL + l;
    #pragma unroll 8
    for (int d = 0; d < DD; d++) {
        float x = base[(size_t)d * LL] + sq[d];
        out[(size_t)d * LL] = tf32r((x - mu) * rs * sg[d] + sb[d]);
    }
}

// ---------------- per (b,d) mean/sd over L of g_h -> g_stat ----------------
__global__ void colstats_kernel() {
    int row = blockIdx.x;            // b*DD + d
    int b = row / DD, d = row % DD;
    const float* src = g_h + (size_t)row * LL;
    float s = 0.f, s2 = 0.f;
    for (int l = threadIdx.x; l < LL; l += 256) {
        float x = src[l];
        s += x; s2 += x * x;
    }
    __shared__ float r1[256], r2[256];
    r1[threadIdx.x] = s; r2[threadIdx.x] = s2;
    __syncthreads();
    for (int o = 128; o > 0; o >>= 1) {
        if (threadIdx.x < o) { r1[threadIdx.x] += r1[threadIdx.x + o]; r2[threadIdx.x] += r2[threadIdx.x + o]; }
        __syncthreads();
    }
    if (threadIdx.x == 0) {
        float mu = r1[0] * (1.f / LL);
        float var = r2[0] * (1.f / LL) - mu * mu;
        var = fmaxf(var, 1e-10f);
        g_stat[b * 2 * DD + d]      = mu;
        g_stat[b * 2 * DD + DD + d] = sqrtf(var);
    }
}

// ------- fused q + qk: qk[b,d] = scale * sum_k wk[k,d] * q[b,k] ------------
__global__ void qqk_kernel(const float* __restrict__ wq,
                           const float* __restrict__ wk) {
    int b = blockIdx.x;
    int tid = threadIdx.x;           // 256 threads, 8 warps
    int warp = tid >> 5, lane = tid & 31;
    __shared__ float st[2 * DD];
    __shared__ float qs[KC];
    for (int e = tid; e < 2 * DD; e += 256) st[e] = g_stat[b * 2 * DD + e];
    __syncthreads();
    #pragma unroll
    for (int jj = 0; jj < 16; jj++) {
        int j = warp * 16 + jj;
        const float* wr = wq + (size_t)j * 2 * DD;
        float acc = 0.f;
        #pragma unroll
        for (int e = lane; e < 2 * DD; e += 32) acc += wr[e] * st[e];
        #pragma unroll
        for (int o = 16; o > 0; o >>= 1) acc += __shfl_xor_sync(0xffffffffu, acc, o);
        if (lane == 0) qs[j] = acc;
    }
    __syncthreads();
    float acc = 0.f;
    #pragma unroll 8
    for (int k = 0; k < KC; k++) acc += wk[(size_t)k * DD + tid] * qs[k];
    g_qk[b * DD + tid] = acc * 0.08838834764831845f;  // 1/sqrt(128)
}

// ------- scores + softmax over L : scores_l = qk . vt_l  (vt = g_h) --------
__global__ void softmax_kernel() {
    int b = blockIdx.x, t = threadIdx.x;   // 1024 threads
    __shared__ float qsh[DD];
    __shared__ float sc[LL];
    __shared__ float red[1024];
    if (t < DD) qsh[t] = g_qk[b * DD + t];
    __syncthreads();
    float lmax = -1e30f;
    for (int l = t; l < LL; l += 1024) {
        const float* hb = g_h + (size_t)b * DD * LL + l;
        float acc = 0.f;
        #pragma unroll 8
        for (int d = 0; d < DD; d++) acc += hb[(size_t)d * LL] * qsh[d];
        sc[l] = acc;
        lmax = fmaxf(lmax, acc);
    }
    red[t] = lmax; __syncthreads();
    for (int o = 512; o > 0; o >>= 1) {
        if (t < o) red[t] = fmaxf(red[t], red[t + o]);
        __syncthreads();
    }
    float m = red[0]; __syncthreads();
    float lsum = 0.f;
    for (int l = t; l < LL; l += 1024) {
        float e = expf(sc[l] - m);
        sc[l] = e; lsum += e;
    }
    red[t] = lsum; __syncthreads();
    for (int o = 512; o > 0; o >>= 1) {
        if (t < o) red[t] += red[t + o];
        __syncthreads();
    }
    float inv = 1.f / red[0];
    for (int l = t; l < LL; l += 1024) g_wsm[b * LL + l] = sc[l] * inv;
}

// ---------------- weighted mean/std over L : g_h,g_wsm -> g_am,g_as --------
__global__ void att_kernel() {
    int row = blockIdx.x;            // b*DD + d
    int b = row / DD;
    const float* src = g_h + (size_t)row * LL;
    const float* w = g_wsm + b * LL;
    float s1 = 0.f, s2 = 0.f;
    for (int l = threadIdx.x; l < LL; l += 256) {
        float x = src[l], ww = w[l];
        s1 += x * ww; s2 += x * x * ww;
    }
    __shared__ float r1[256], r2[256];
    r1[threadIdx.x] = s1; r2[threadIdx.x] = s2;
    __syncthreads();
    for (int o = 128; o > 0; o >>= 1) {
        if (threadIdx.x < o) { r1[threadIdx.x] += r1[threadIdx.x + o]; r2[threadIdx.x] += r2[threadIdx.x + o]; }
        __syncthreads();
    }
    if (threadIdx.x == 0) {
        float mean = r1[0];
        float var = fmaxf(r2[0] - mean * mean, 1e-10f);
        g_am[row] = mean;
        g_as[row] = sqrtf(var);
    }
}

// ---------------- skip accumulate + qadd : warp-per-output -----------------
__global__ void skip_kernel(const float* __restrict__ fc_w,
                            const float* __restrict__ fc_b,
                            const float* __restrict__ fcq_w,
                            int first) {
    int b = blockIdx.x;
    int warp = threadIdx.x >> 5, lane = threadIdx.x & 31;
    __shared__ float sm[DD], ss[DD];
    sm[threadIdx.x] = g_am[b * DD + threadIdx.x];
    ss[threadIdx.x] = g_as[b * DD + threadIdx.x];
    __syncthreads();
    int o = blockIdx.y * 64 + warp * 8;  // 4 y-blocks x 8 warps x 8 outputs
    for (int oo = o; oo < o + 8; oo++) {
        const float* fr = fc_w + (size_t)oo * 2 * DD;
        const float* qr = fcq_w + (size_t)oo * DD;
        float accs = 0.f, accq = 0.f;
        #pragma unroll
        for (int d = lane; d < DD; d += 32) {
            accs += fr[d] * sm[d] + fr[DD + d] * ss[d];
            accq += qr[d] * sm[d];
        }
        #pragma unroll
        for (int sh = 16; sh > 0; sh >>= 1) {
            accs += __shfl_xor_sync(0xffffffffu, accs, sh);
            accq += __shfl_xor_sync(0xffffffffu, accq, sh);
        }
        if (lane == 0) {
            float prev = first ? 0.f : g_skip[b * DD + oo];
            g_skip[b * DD + oo] = prev + accs + fc_b[oo];
            g_qadd[b * DD + oo] = accq;
        }
    }
}

// =================== fused FFN: v = w2 @ relu(w1 @ h + b1) + b2 + f_in =====
// CTA: 128 threads (4 warps), out tile 256(D) x 64(L). Per cc chunk (128 h1
// rows): phase1 computes h1c = relu(w1[cc] @ h_tile + b1) (warp tiles 64x32),
// rounds to tf32, parks in smem (stride 72: conflict-free); phase2 does
// out += w2[:,cc] @ h1c with 64x64 warp tiles (B-frags straight from smem).
// h1 never touches DRAM. Epilogue adds b2 + (v_old + qadd) and writes g_v.
#define FN 64
#define H1S 72                         /* h1_s col stride: 72%32==8 */
#define OFF_U 9216                     /* h1_s = 128*72 floats */
#define PH1_STG 3712                   /* 128*20 + 16*72 */
#define PH2_STG 5120                   /* 256*20 */
#define FFN_SMEM ((OFF_U + 3 * PH2_STG) * 4)   /* 98304 B */

__device__ __forceinline__ void cp16(unsigned dst, const float* src) {
    asm volatile("cp.async.cg.shared.global [%0], [%1], 16;" :: "r"(dst), "l"(src));
}

__global__ void __launch_bounds__(128, 2)
ffn_fused(const float* __restrict__ w1g, const float* __restrict__ b1g,
          const float* __restrict__ w2g, const float* __restrict__ b2g) {
    extern __shared__ float smem[];
    const int b  = blockIdx.z;
    const int n0 = blockIdx.x * FN;
    const int tid = threadIdx.x;
    const int warp = tid >> 5, lane = tid & 31;
    const unsigned sbase = (unsigned)__cvta_generic_to_shared(smem);
    const float* hb = g_h + (size_t)b * DD * LL;
    // ph1 warp tiling: 2x2 grid of 64x32 over (128 x 64)
    const int wm1 = (warp & 1) * 64;
    const int wn1 = (warp >> 1) * 32;

    float c2[4][8][4];
    #pragma unroll
    for (int i = 0; i < 4; i++)
        #pragma unroll
        for (int j = 0; j < 8; j++)
            #pragma unroll
            for (int r = 0; r < 4; r++) c2[i][j][r] = 0.f;

    for (int cc = 0; cc < 4; cc++) {
        // ================= phase 1: h1c = relu(w1[cc] @ h_tile + b1) =======
        float c1[4][4][4];
        #pragma unroll
        for (int i = 0; i < 4; i++)
            #pragma unroll
            for (int j = 0; j < 4; j++)
                #pragma unroll
                for (int r = 0; r < 4; r++) c1[i][j][r] = 0.f;

        const float* w1c = w1g + (size_t)(cc * 128) * DD;
        auto load1 = [&](int it, int stg) {
            unsigned ab = sbase + (unsigned)(OFF_U + stg * PH1_STG) * 4u;
            unsigned bb = ab + 2560u * 4u;
            int k0 = it * 16;
            int ak = (tid & 3) * 4;
            #pragma unroll
            for (int h = 0; h < 4; h++) {
                int m = (tid >> 2) + h * 32;
                cp16(ab + (unsigned)(m * 20 + ak) * 4u, w1c + (size_t)m * DD + k0 + ak);
            }
            int bc = (tid & 15) * 4;
            #pragma unroll
            for (int h = 0; h < 2; h++) {
                int kr = (tid >> 4) + h * 8;
                cp16(bb + (unsigned)(kr * H1S + bc) * 4u,
                     hb + (size_t)(k0 + kr) * LL + n0 + bc);
            }
        };
        load1(0, 0); asm volatile("cp.async.commit_group;");
        load1(1, 1); asm volatile("cp.async.commit_group;");
        for (int i = 0; i < 16; i++) {
            asm volatile("cp.async.wait_group 1;");
            __syncthreads();
            if (i + 2 < 16) load1(i + 2, (i + 2) % 3);
            asm volatile("cp.async.commit_group;");
            const float* as_ = smem + OFF_U + (i % 3) * PH1_STG;
            const float* bs_ = as_ + 2560;
            #pragma unroll
            for (int kk = 0; kk < 16; kk += 8) {
                unsigned af[4][4], bf[4][2];
                #pragma unroll
                for (int mi = 0; mi < 4; mi++) {
                    int r = wm1 + mi * 16 + (lane >> 2);
                    int kcol = kk + (lane & 3);
                    af[mi][0] = __float_as_uint(as_[ r      * 20 + kcol    ]);
                    af[mi][1] = __float_as_uint(as_[(r + 8) * 20 + kcol    ]);
                    af[mi][2] = __float_as_uint(as_[ r      * 20 + kcol + 4]);
                    af[mi][3] = __float_as_uint(as_[(r + 8) * 20 + kcol + 4]);
                }
                #pragma unroll
                for (int ni = 0; ni < 4; ni++) {
                    int col = wn1 + ni * 8 + (lane >> 2);
                    int kr = kk + (lane & 3);
                    bf[ni][0] = __float_as_uint(bs_[ kr      * H1S + col]);
                    bf[ni][1] = __float_as_uint(bs_[(kr + 4) * H1S + col]);
                }
                #pragma unroll
                for (int mi = 0; mi < 4; mi++)
                    #pragma unroll
                    for (int ni = 0; ni < 4; ni++) {
                        asm volatile(
                            "mma.sync.aligned.m16n8k8.row.col.f32.tf32.tf32.f32 "
                            "{%0,%1,%2,%3}, {%4,%5,%6,%7}, {%8,%9}, {%0,%1,%2,%3};"
                            : "+f"(c1[mi][ni][0]), "+f"(c1[mi][ni][1]),
                              "+f"(c1[mi][ni][2]), "+f"(c1[mi][ni][3])
                            : "r"(af[mi][0]), "r"(af[mi][1]), "r"(af[mi][2]), "r"(af[mi][3]),
                              "r"(bf[ni][0]), "r"(bf[ni][1]));
                    }
            }
        }
        asm volatile("cp.async.wait_group 0;");
        __syncthreads();
        // ---- ph1 epilogue: relu + bias, tf32-round, park in h1_s ----
        #pragma unroll
        for (int mi = 0; mi < 4; mi++) {
            int row = wm1 + mi * 16 + (lane >> 2);
            float bv0 = b1g[cc * 128 + row];
            float bv1 = b1g[cc * 128 + row + 8];
            #pragma unroll
            for (int ni = 0; ni < 4; ni++) {
                int col = wn1 + ni * 8 + (lane & 3) * 2;
                float v0 = tf32r(fmaxf(c1[mi][ni][0] + bv0, 0.f));
                float v1 = tf32r(fmaxf(c1[mi][ni][1] + bv0, 0.f));
                float v2 = tf32r(fmaxf(c1[mi][ni][2] + bv1, 0.f));
                float v3 = tf32r(fmaxf(c1[mi][ni][3] + bv1, 0.f));
                *(float2*)&smem[ row      * H1S + col] = make_float2(v0, v1);
                *(float2*)&smem[(row + 8) * H1S + col] = make_float2(v2, v3);
            }
        }
        __syncthreads();

        // ================= phase 2: out += w2[:, cc*128:] @ h1c ============
        auto load2 = [&](int it, int stg) {
            unsigned ab = sbase + (unsigned)(OFF_U + stg * PH2_STG) * 4u;
            int k0 = cc * 128 + it * 16;
            int ak = (tid & 3) * 4;
            #pragma unroll
            for (int h = 0; h < 8; h++) {
                int m = (tid >> 2) + h * 32;
                cp16(ab + (unsigned)(m * 20 + ak) * 4u, w2g + (size_t)m * HH + k0 + ak);
            }
        };
        load2(0, 0); asm volatile("cp.async.commit_group;");
        load2(1, 1); asm volatile("cp.async.commit_group;");
        for (int i = 0; i < 8; i++) {
            asm volatile("cp.async.wait_group 1;");
            __syncthreads();
            if (i + 2 < 8) load2(i + 2, (i + 2) % 3);
            asm volatile("cp.async.commit_group;");
            const float* as_ = smem + OFF_U + (i % 3) * PH2_STG;
            const float* h1s = smem + i * 16 * H1S;
            #pragma unroll
            for (int kk = 0; kk < 16; kk += 8) {
                unsigned af[4][4], bf[8][2];
                #pragma unroll
                for (int mi = 0; mi < 4; mi++) {
                    int r = warp * 64 + mi * 16 + (lane >> 2);
                    int kcol = kk + (lane & 3);
                    af[mi][0] = __float_as_uint(as_[ r      * 20 + kcol    ]);
                    af[mi][1] = __float_as_uint(as_[(r + 8) * 20 + kcol    ]);
                    af[mi][2] = __float_as_uint(as_[ r      * 20 + kcol + 4]);
                    af[mi][3] = __float_as_uint(as_[(r + 8) * 20 + kcol + 4]);
                }
                #pragma unroll
                for (int ni = 0; ni < 8; ni++) {
                    int col = ni * 8 + (lane >> 2);
                    int kr = kk + (lane & 3);
                    bf[ni][0] = __float_as_uint(h1s[ kr      * H1S + col]);
                    bf[ni][1] = __float_as_uint(h1s[(kr + 4) * H1S + col]);
                }
                #pragma unroll
                for (int mi = 0; mi < 4; mi++)
                    #pragma unroll
                    for (int ni = 0; ni < 8; ni++) {
                        asm volatile(
                            "mma.sync.aligned.m16n8k8.row.col.f32.tf32.tf32.f32 "
                            "{%0,%1,%2,%3}, {%4,%5,%6,%7}, {%8,%9}, {%0,%1,%2,%3};"
                            : "+f"(c2[mi][ni][0]), "+f"(c2[mi][ni][1]),
                              "+f"(c2[mi][ni][2]), "+f"(c2[mi][ni][3])
                            : "r"(af[mi][0]), "r"(af[mi][1]), "r"(af[mi][2]), "r"(af[mi][3]),
                              "r"(bf[ni][0]), "r"(bf[ni][1]));
                    }
            }
        }
        asm volatile("cp.async.wait_group 0;");
        __syncthreads();
    }

    // ================= final epilogue: + b2 + (v_old + qadd) -> g_v ========
    float* vb = g_v + (size_t)b * DD * LL;
    const float* qa = g_qadd + b * DD;
    #pragma unroll
    for (int mi = 0; mi < 4; mi++) {
        int row = warp * 64 + mi * 16 + (lane >> 2);
        float a0 = b2g[row] + qa[row];
        float a1 = b2g[row + 8] + qa[row + 8];
        #pragma unroll
        for (int ni = 0; ni < 8; ni++) {
            int col = n0 + ni * 8 + (lane & 3) * 2;
            size_t i0 = (size_t)row * LL + col;
            size_t i1 = (size_t)(row + 8) * LL + col;
            float2 p0 = *(const float2*)&vb[i0];
            float2 p1 = *(const float2*)&vb[i1];
            *(float2*)&vb[i0] = make_float2(c2[mi][ni][0] + a0 + p0.x,
                                            c2[mi][ni][1] + a0 + p0.y);
            *(float2*)&vb[i1] = make_float2(c2[mi][ni][2] + a1 + p1.x,
                                            c2[mi][ni][3] + a1 + p1.y);
        }
    }
}

// ---------------- final relu + BatchNorm over batch -> out -----------------
__global__ void bn_kernel(float* __restrict__ out) {
    int d = blockIdx.x;        // 0..255
    int b = threadIdx.x;       // 0..63
    __shared__ float r1[64], r2[64];
    float y = fmaxf(g_skip[b * DD + d], 0.f);
    r1[b] = y; r2[b] = y * y;
    __syncthreads();
    for (int o = 32; o > 0; o >>= 1) {
        if (b < o) { r1[b] += r1[b + o]; r2[b] += r2[b + o]; }
        __syncthreads();
    }
    float mu = r1[0] * (1.f / 64.f);
    float var = r2[0] * (1.f / 64.f) - mu * mu;
    float rs = rsqrtf(var + 1e-5f);
    out[b * DD + d] = (y - mu) * rs;
}

// ---------------- launch ----------------
extern "C" void kernel_launch(void* const* d_in, const int* in_sizes, int n_in,
                              void* d_out, int out_size) {
    const float* x      = (const float*)d_in[0];
    const float* wk     = (const float*)d_in[1];
    const float* wq     = (const float*)d_in[2];
    const float* fcq_w  = (const float*)d_in[3];
    const float* fc_w   = (const float*)d_in[4];
    const float* fc_b   = (const float*)d_in[5];
    const float* att_g  = (const float*)d_in[6];
    const float* att_b  = (const float*)d_in[7];
    const float* w1     = (const float*)d_in[8];
    const float* b1     = (const float*)d_in[9];
    const float* w2     = (const float*)d_in[10];
    const float* b2     = (const float*)d_in[11];
    const float* ffw_g  = (const float*)d_in[12];
    const float* ffw_b  = (const float*)d_in[13];
    float* out = (float*)d_out;

    float *p_v, *p_w1, *p_w2;
    cudaGetSymbolAddress((void**)&p_v,  g_v);
    cudaGetSymbolAddress((void**)&p_w1, g_w1);
    cudaGetSymbolAddress((void**)&p_w2, g_w2);

    cudaFuncSetAttribute(ffn_fused,
                         cudaFuncAttributeMaxDynamicSharedMemorySize, FFN_SMEM);

    prep_kernel<<<512, 256>>>(w1, w2);

    for (int i = 0; i < 2; i++) {
        const float* vsrc = (i == 0) ? x : (const float*)p_v;
        att_ln_kernel<<<BB * LL / 256, 256>>>(vsrc, att_g + i * DD, att_b + i * DD);
        colstats_kernel<<<BB * DD, 256>>>();
        qqk_kernel<<<BB, 256>>>(wq + (size_t)i * KC * 2 * DD,
                                wk + (size_t)i * KC * DD);
        softmax_kernel<<<BB, 1024>>>();
        att_kernel<<<BB * DD, 256>>>();
        skip_kernel<<<dim3(BB, 4), 256>>>(fc_w + (size_t)i * DD * 2 * DD,
                                          fc_b + (size_t)i * DD,
                                          fcq_w + (size_t)i * DD * DD, i == 0);
        ffn_ln_kernel<<<BB * LL / 256, 256>>>(vsrc, ffw_g + i * DD, ffw_b + i * DD);
        // NOTE on first block: g_v holds uninitialized data but ffn_fused
        // reads v_old from g_v... must seed g_v = x for i==0. ffn_ln reads
        // vsrc (=x) but ffn_fused reads g_v. Seed via the epilogue source:
        // handled below by pointer choice impossible -> copy once.
        if (i == 0) {
            // one-time async copy x -> g_v so the i=0 epilogue residual is x
            cudaMemcpyAsync(p_v, x, (size_t)BB * DD * LL * sizeof(float),
                            cudaMemcpyDeviceToDevice);
        }
        ffn_fused<<<dim3(LL / FN, 1, BB), 128, FFN_SMEM>>>(
            p_w1 + (size_t)i * HH * DD, b1 + (size_t)i * HH,
            p_w2 + (size_t)i * DD * HH, b2 + (size_t)i * DD);
    }

    bn_kernel<<<DD, 64>>>(out);
}